// round 8
// baseline (speedup 1.0000x reference)
#include <cuda_runtime.h>
#include <math.h>

#define N_V    100000
#define NE_    20000
#define NNZ_   1600000
#define NFEAT_ 128
#define NHID_  64
#define NCLASS_ 40
#define NLAYER_ 4

// ---------------- device scratch (static, no allocation) ----------------
__device__ float g_X [N_V * NHID_];   // current features
__device__ float g_X0[N_V * NHID_];   // residual anchor
__device__ float g_Xe[NE_ * NHID_];   // edge features (pre-scaled by degE/count)
__device__ float g_escale[NE_];
__device__ int   g_cntE[NE_];
__device__ int   g_cntV[N_V];
__device__ int   g_lenE[NE_];
__device__ int   g_lenV[N_V];
__device__ int   g_offE[NE_];
__device__ int   g_offV[N_V];
__device__ int   g_curE;
__device__ int   g_curV;
__device__ int   g_adjE[NNZ_];        // members (vertex ids) per edge
__device__ int   g_adjV[NNZ_];        // incident edges per vertex

// ---------------- CSR build ----------------
__global__ void zero_cnt_k() {
    int i = blockIdx.x * blockDim.x + threadIdx.x;
    if (i < NE_) g_cntE[i] = 0;
    if (i < N_V) g_cntV[i] = 0;
    if (i == 0) { g_curE = 0; g_curV = 0; }
}

__global__ void hist_k(const int4* __restrict__ vertex4, const int4* __restrict__ edges4) {
    int i = blockIdx.x * blockDim.x + threadIdx.x;
    if (i < NNZ_ / 4) {
        int4 e = edges4[i];
        int4 v = vertex4[i];
        atomicAdd(&g_cntE[e.x], 1);
        atomicAdd(&g_cntE[e.y], 1);
        atomicAdd(&g_cntE[e.z], 1);
        atomicAdd(&g_cntE[e.w], 1);
        atomicAdd(&g_cntV[v.x], 1);
        atomicAdd(&g_cntV[v.y], 1);
        atomicAdd(&g_cntV[v.z], 1);
        atomicAdd(&g_cntV[v.w], 1);
    }
}

// warp-aggregated bump allocation of CSR offsets (segment order arbitrary but
// valid; per-segment sums are order-independent).
__global__ void alloc_k(const float* __restrict__ degE) {
    int i = blockIdx.x * blockDim.x + threadIdx.x;
    const int n = NE_ + N_V;
    if (i >= n) return;           // NE_ and n are multiples of 32
    int lane = threadIdx.x & 31;
    bool isE = (i < NE_);
    int c = isE ? g_cntE[i] : g_cntV[i - NE_];
    int inc = c;
    #pragma unroll
    for (int o = 1; o < 32; o <<= 1) {
        int t = __shfl_up_sync(0xffffffffu, inc, o);
        if (lane >= o) inc += t;
    }
    int base = 0;
    if (lane == 31)
        base = atomicAdd(isE ? &g_curE : &g_curV, inc);
    base = __shfl_sync(0xffffffffu, base, 31);
    int off = base + inc - c;
    if (isE) {
        g_offE[i] = off;
        g_lenE[i] = c;
        g_escale[i] = degE[i] / fmaxf((float)c, 1.0f);
        g_cntE[i] = 0;
    } else {
        g_offV[i - NE_] = off;
        g_lenV[i - NE_] = c;
        g_cntV[i - NE_] = 0;
    }
}

__global__ void build_adj_k(const int4* __restrict__ vertex4, const int4* __restrict__ edges4) {
    int i = blockIdx.x * blockDim.x + threadIdx.x;
    if (i < NNZ_ / 4) {
        int4 v = vertex4[i];
        int4 e = edges4[i];
        int oe0 = g_offE[e.x], oe1 = g_offE[e.y], oe2 = g_offE[e.z], oe3 = g_offE[e.w];
        int ov0 = g_offV[v.x], ov1 = g_offV[v.y], ov2 = g_offV[v.z], ov3 = g_offV[v.w];
        int pe0 = oe0 + atomicAdd(&g_cntE[e.x], 1);
        int pe1 = oe1 + atomicAdd(&g_cntE[e.y], 1);
        int pe2 = oe2 + atomicAdd(&g_cntE[e.z], 1);
        int pe3 = oe3 + atomicAdd(&g_cntE[e.w], 1);
        int pv0 = ov0 + atomicAdd(&g_cntV[v.x], 1);
        int pv1 = ov1 + atomicAdd(&g_cntV[v.y], 1);
        int pv2 = ov2 + atomicAdd(&g_cntV[v.z], 1);
        int pv3 = ov3 + atomicAdd(&g_cntV[v.w], 1);
        g_adjE[pe0] = v.x; g_adjE[pe1] = v.y; g_adjE[pe2] = v.z; g_adjE[pe3] = v.w;
        g_adjV[pv0] = e.x; g_adjV[pv1] = e.y; g_adjV[pv2] = e.z; g_adjV[pv3] = e.w;
    }
}

// ---------------- vertex -> edge mean (warp per edge, float2 lanes) ----------------
__global__ void __launch_bounds__(256) agg_ve_k() {
    int e = blockIdx.x * 8 + (threadIdx.x >> 5);
    if (e >= NE_) return;
    int lane = threadIdx.x & 31;
    int beg = g_offE[e], len = g_lenE[e];
    float ax = 0.f, ay = 0.f;
    const float* __restrict__ X = g_X;
    int j = 0;
    for (; j + 8 <= len; j += 8) {
        int i0 = g_adjE[beg + j + 0], i1 = g_adjE[beg + j + 1];
        int i2 = g_adjE[beg + j + 2], i3 = g_adjE[beg + j + 3];
        int i4 = g_adjE[beg + j + 4], i5 = g_adjE[beg + j + 5];
        int i6 = g_adjE[beg + j + 6], i7 = g_adjE[beg + j + 7];
        float2 t0 = __ldg((const float2*)&X[i0 * NHID_ + lane * 2]);
        float2 t1 = __ldg((const float2*)&X[i1 * NHID_ + lane * 2]);
        float2 t2 = __ldg((const float2*)&X[i2 * NHID_ + lane * 2]);
        float2 t3 = __ldg((const float2*)&X[i3 * NHID_ + lane * 2]);
        float2 t4 = __ldg((const float2*)&X[i4 * NHID_ + lane * 2]);
        float2 t5 = __ldg((const float2*)&X[i5 * NHID_ + lane * 2]);
        float2 t6 = __ldg((const float2*)&X[i6 * NHID_ + lane * 2]);
        float2 t7 = __ldg((const float2*)&X[i7 * NHID_ + lane * 2]);
        ax += ((t0.x + t1.x) + (t2.x + t3.x)) + ((t4.x + t5.x) + (t6.x + t7.x));
        ay += ((t0.y + t1.y) + (t2.y + t3.y)) + ((t4.y + t5.y) + (t6.y + t7.y));
    }
    for (; j < len; j++) {
        int v = g_adjE[beg + j];
        float2 t = __ldg((const float2*)&X[v * NHID_ + lane * 2]);
        ax += t.x; ay += t.y;
    }
    float s = g_escale[e];
    float2 r; r.x = ax * s; r.y = ay * s;
    *(float2*)&g_Xe[e * NHID_ + lane * 2] = r;
}

// ---------------- edge -> vertex sum (warp per vertex, float2 lanes),
//                  fused *degV, L2 norm (shuffle-only), alpha-mix ----------------
__global__ void __launch_bounds__(256) agg_ev_k(const float* __restrict__ degV) {
    int v = blockIdx.x * 8 + (threadIdx.x >> 5);
    if (v >= N_V) return;
    int lane = threadIdx.x & 31;
    int beg = g_offV[v], len = g_lenV[v];
    float ax = 0.f, ay = 0.f;
    const float* __restrict__ Xe = g_Xe;
    int j = 0;
    for (; j + 8 <= len; j += 8) {
        int e0 = g_adjV[beg + j + 0], e1 = g_adjV[beg + j + 1];
        int e2 = g_adjV[beg + j + 2], e3 = g_adjV[beg + j + 3];
        int e4 = g_adjV[beg + j + 4], e5 = g_adjV[beg + j + 5];
        int e6 = g_adjV[beg + j + 6], e7 = g_adjV[beg + j + 7];
        float2 t0 = __ldg((const float2*)&Xe[e0 * NHID_ + lane * 2]);
        float2 t1 = __ldg((const float2*)&Xe[e1 * NHID_ + lane * 2]);
        float2 t2 = __ldg((const float2*)&Xe[e2 * NHID_ + lane * 2]);
        float2 t3 = __ldg((const float2*)&Xe[e3 * NHID_ + lane * 2]);
        float2 t4 = __ldg((const float2*)&Xe[e4 * NHID_ + lane * 2]);
        float2 t5 = __ldg((const float2*)&Xe[e5 * NHID_ + lane * 2]);
        float2 t6 = __ldg((const float2*)&Xe[e6 * NHID_ + lane * 2]);
        float2 t7 = __ldg((const float2*)&Xe[e7 * NHID_ + lane * 2]);
        ax += ((t0.x + t1.x) + (t2.x + t3.x)) + ((t4.x + t5.x) + (t6.x + t7.x));
        ay += ((t0.y + t1.y) + (t2.y + t3.y)) + ((t4.y + t5.y) + (t6.y + t7.y));
    }
    for (; j < len; j++) {
        int e = g_adjV[beg + j];
        float2 t = __ldg((const float2*)&Xe[e * NHID_ + lane * 2]);
        ax += t.x; ay += t.y;
    }
    float dv = __ldg(&degV[v]);
    ax *= dv; ay *= dv;
    float ss = ax * ax + ay * ay;
    #pragma unroll
    for (int o = 16; o; o >>= 1) ss += __shfl_xor_sync(0xffffffffu, ss, o);
    float scale = (ss > 0.f) ? rsqrtf(ss) : 0.f;
    float2 x0 = *(const float2*)&g_X0[(size_t)v * NHID_ + lane * 2];
    float2 r;
    r.x = 0.9f * ax * scale + 0.1f * x0.x;
    r.y = 0.9f * ay * scale + 0.1f * x0.y;
    *(float2*)&g_X[(size_t)v * NHID_ + lane * 2] = r;
}

// ---------------- tiled GEMM: 64-row tile, 128 threads, 4x8 micro-tile ----------------
template <int K, int NCOL, int MODE>
__global__ void __launch_bounds__(128) gemm_k(
    const float* __restrict__ Aext, const float* __restrict__ W,
    const float* __restrict__ bias, float* __restrict__ outext,
    float c0, float c1)
{
    constexpr int KC = 64;
    constexpr int KP = KC + 4;
    constexpr int NP = (NCOL + 7) & ~3;
    __shared__ float As[64 * KP];
    __shared__ float Wsm[KC * NP];
    __shared__ float Ls[(MODE == 2) ? 64 * NCOL : 1];

    const float* A = (MODE == 0) ? Aext : g_X;
    const int M = N_V;
    int tid = threadIdx.x;
    int row0 = blockIdx.x * 64;
    int tx = tid & 7;
    int ty = tid >> 3;
    bool active = (NCOL == 64) || (tx * 8 < NCOL);

    float acc[4][8] = {};

    for (int kc = 0; kc < K; kc += KC) {
        for (int idx = tid; idx < KC * (NCOL / 4); idx += 128) {
            int k = idx / (NCOL / 4), c4 = idx - k * (NCOL / 4);
            *(float4*)&Wsm[k * NP + c4 * 4] = *(const float4*)&W[(kc + k) * NCOL + c4 * 4];
        }
        for (int idx = tid; idx < 64 * (KC / 4); idx += 128) {
            int r = idx / (KC / 4), k4 = idx - r * (KC / 4);
            int row = row0 + r;
            float4 v = make_float4(0.f, 0.f, 0.f, 0.f);
            if (row < M) v = *(const float4*)&A[(size_t)row * K + kc + k4 * 4];
            *(float4*)&As[r * KP + k4 * 4] = v;
        }
        __syncthreads();
        if (active) {
            #pragma unroll 4
            for (int k = 0; k < KC; k++) {
                float4 w0 = *(const float4*)&Wsm[k * NP + tx * 8];
                float4 w1 = *(const float4*)&Wsm[k * NP + tx * 8 + 4];
                #pragma unroll
                for (int i = 0; i < 4; i++) {
                    float a = As[(ty * 4 + i) * KP + k];
                    acc[i][0] += a * w0.x; acc[i][1] += a * w0.y;
                    acc[i][2] += a * w0.z; acc[i][3] += a * w0.w;
                    acc[i][4] += a * w1.x; acc[i][5] += a * w1.y;
                    acc[i][6] += a * w1.z; acc[i][7] += a * w1.w;
                }
            }
        }
        __syncthreads();
    }

    if (MODE == 0) {
        float4 ba = *(const float4*)&bias[tx * 8];
        float4 bb = *(const float4*)&bias[tx * 8 + 4];
        #pragma unroll
        for (int i = 0; i < 4; i++) {
            int row = row0 + ty * 4 + i;
            if (row < M) {
                float4 ra, rb;
                ra.x = fmaxf(acc[i][0] + ba.x, 0.f);
                ra.y = fmaxf(acc[i][1] + ba.y, 0.f);
                ra.z = fmaxf(acc[i][2] + ba.z, 0.f);
                ra.w = fmaxf(acc[i][3] + ba.w, 0.f);
                rb.x = fmaxf(acc[i][4] + bb.x, 0.f);
                rb.y = fmaxf(acc[i][5] + bb.y, 0.f);
                rb.z = fmaxf(acc[i][6] + bb.z, 0.f);
                rb.w = fmaxf(acc[i][7] + bb.w, 0.f);
                *(float4*)&g_X [(size_t)row * NHID_ + tx * 8]     = ra;
                *(float4*)&g_X [(size_t)row * NHID_ + tx * 8 + 4] = rb;
                *(float4*)&g_X0[(size_t)row * NHID_ + tx * 8]     = ra;
                *(float4*)&g_X0[(size_t)row * NHID_ + tx * 8 + 4] = rb;
            }
        }
    } else if (MODE == 1) {
        #pragma unroll
        for (int i = 0; i < 4; i++) {
            int r = ty * 4 + i;
            int row = row0 + r;
            if (row < M) {
                float4 ra, rb;
                ra.x = fmaxf(c0 * As[r * KP + tx * 8 + 0] + c1 * acc[i][0], 0.f);
                ra.y = fmaxf(c0 * As[r * KP + tx * 8 + 1] + c1 * acc[i][1], 0.f);
                ra.z = fmaxf(c0 * As[r * KP + tx * 8 + 2] + c1 * acc[i][2], 0.f);
                ra.w = fmaxf(c0 * As[r * KP + tx * 8 + 3] + c1 * acc[i][3], 0.f);
                rb.x = fmaxf(c0 * As[r * KP + tx * 8 + 4] + c1 * acc[i][4], 0.f);
                rb.y = fmaxf(c0 * As[r * KP + tx * 8 + 5] + c1 * acc[i][5], 0.f);
                rb.z = fmaxf(c0 * As[r * KP + tx * 8 + 6] + c1 * acc[i][6], 0.f);
                rb.w = fmaxf(c0 * As[r * KP + tx * 8 + 7] + c1 * acc[i][7], 0.f);
                *(float4*)&g_X[(size_t)row * NHID_ + tx * 8]     = ra;
                *(float4*)&g_X[(size_t)row * NHID_ + tx * 8 + 4] = rb;
            }
        }
    } else {
        if (active) {
            #pragma unroll
            for (int i = 0; i < 4; i++) {
                int r = ty * 4 + i;
                #pragma unroll
                for (int j = 0; j < 8; j++)
                    Ls[r * NCOL + tx * 8 + j] = acc[i][j] + __ldg(bias + tx * 8 + j);
            }
        }
        __syncthreads();
        if (tid < 64) {
            int row = row0 + tid;
            if (row < M) {
                float mx = -1e30f;
                #pragma unroll
                for (int c = 0; c < NCOL; c++) mx = fmaxf(mx, Ls[tid * NCOL + c]);
                float s = 0.f;
                #pragma unroll
                for (int c = 0; c < NCOL; c++) s += __expf(Ls[tid * NCOL + c] - mx);
                float lse = mx + __logf(s);
                #pragma unroll
                for (int c = 0; c < NCOL; c++)
                    outext[(size_t)row * NCOL + c] = Ls[tid * NCOL + c] - lse;
            }
        }
    }
}

// ---------------- launch ----------------
extern "C" void kernel_launch(void* const* d_in, const int* in_sizes, int n_in,
                              void* d_out, int out_size)
{
    const float* x    = (const float*)d_in[0];
    const float* degE = (const float*)d_in[1];
    const float* degV = (const float*)d_in[2];
    const float* W0   = (const float*)d_in[3];
    const float* b0   = (const float*)d_in[4];
    const float* Ws   = (const float*)d_in[5];
    const float* Wout = (const float*)d_in[6];
    const float* bout = (const float*)d_in[7];
    const int* vertex = (const int*)d_in[8];
    const int* edges  = (const int*)d_in[9];
    float* out = (float*)d_out;

    (void)in_sizes; (void)n_in; (void)out_size;

    const int GB = (N_V + 63) / 64;
    const int Q4 = NNZ_ / 4;

    // CSR/CSC build
    zero_cnt_k<<<(N_V + 255) / 256, 256>>>();
    hist_k<<<(Q4 + 255) / 256, 256>>>((const int4*)vertex, (const int4*)edges);
    alloc_k<<<(NE_ + N_V + 255) / 256, 256>>>(degE);
    build_adj_k<<<(Q4 + 255) / 256, 256>>>((const int4*)vertex, (const int4*)edges);

    // X = relu(x @ W0 + b0); X0 = X
    gemm_k<128, 64, 0><<<GB, 128>>>(x, W0, b0, nullptr, 0.f, 0.f);

    // MEASUREMENT ROUND: each agg pass launched TWICE (idempotent pure
    // functions; ve,ve,ev,ev order keeps inputs fixed between duplicates;
    // output is bitwise identical). dur delta / 8 = true per-pass agg cost.
    for (int i = 0; i < NLAYER_; i++) {
        float beta = logf(0.5f / (float)(i + 1) + 1.0f);
        agg_ve_k<<<(NE_ + 7) / 8, 256>>>();
        agg_ve_k<<<(NE_ + 7) / 8, 256>>>();   // duplicate (diagnostic)
        agg_ev_k<<<(N_V + 7) / 8, 256>>>(degV);
        agg_ev_k<<<(N_V + 7) / 8, 256>>>(degV);   // duplicate (diagnostic)
        gemm_k<64, 64, 1><<<GB, 128>>>(nullptr, Ws + (size_t)i * NHID_ * NHID_,
                                       nullptr, nullptr, 1.0f - beta, beta);
    }

    // log_softmax(X @ Wout + bout)
    gemm_k<64, 40, 2><<<GB, 128>>>(nullptr, Wout, bout, out, 0.f, 0.f);
}

// round 9
// speedup vs baseline: 1.2282x; 1.2282x over previous
#include <cuda_runtime.h>
#include <math.h>

#define N_V    100000
#define NE_    20000
#define NNZ_   1600000
#define NFEAT_ 128
#define NHID_  64
#define NCLASS_ 40
#define NLAYER_ 4

// ---------------- device scratch (static, no allocation) ----------------
__device__ float g_X [N_V * NHID_];   // current features
__device__ float g_X0[N_V * NHID_];   // residual anchor
__device__ float g_Xe[NE_ * NHID_];   // edge features (pre-scaled by degE/count)
__device__ float g_escale[NE_];
__device__ int   g_cntE[NE_];
__device__ int   g_cntV[N_V];
__device__ int   g_lenE[NE_];
__device__ int   g_lenV[N_V];
__device__ int   g_offE[NE_];
__device__ int   g_offV[N_V];
__device__ int   g_curE;
__device__ int   g_curV;
__device__ int   g_adjE[NNZ_];        // members (vertex ids) per edge
__device__ int   g_adjV[NNZ_];        // incident edges per vertex

// ---------------- CSR build ----------------
__global__ void zero_cnt_k() {
    int i = blockIdx.x * blockDim.x + threadIdx.x;
    if (i < NE_) g_cntE[i] = 0;
    if (i < N_V) g_cntV[i] = 0;
    if (i == 0) { g_curE = 0; g_curV = 0; }
}

__global__ void hist_k(const int4* __restrict__ vertex4, const int4* __restrict__ edges4) {
    int i = blockIdx.x * blockDim.x + threadIdx.x;
    if (i < NNZ_ / 4) {
        int4 e = edges4[i];
        int4 v = vertex4[i];
        atomicAdd(&g_cntE[e.x], 1);
        atomicAdd(&g_cntE[e.y], 1);
        atomicAdd(&g_cntE[e.z], 1);
        atomicAdd(&g_cntE[e.w], 1);
        atomicAdd(&g_cntV[v.x], 1);
        atomicAdd(&g_cntV[v.y], 1);
        atomicAdd(&g_cntV[v.z], 1);
        atomicAdd(&g_cntV[v.w], 1);
    }
}

// warp-aggregated bump allocation of CSR offsets (segment order arbitrary but
// valid; per-segment sums are order-independent).
__global__ void alloc_k(const float* __restrict__ degE) {
    int i = blockIdx.x * blockDim.x + threadIdx.x;
    const int n = NE_ + N_V;
    if (i >= n) return;           // NE_ and n are multiples of 32
    int lane = threadIdx.x & 31;
    bool isE = (i < NE_);
    int c = isE ? g_cntE[i] : g_cntV[i - NE_];
    int inc = c;
    #pragma unroll
    for (int o = 1; o < 32; o <<= 1) {
        int t = __shfl_up_sync(0xffffffffu, inc, o);
        if (lane >= o) inc += t;
    }
    int base = 0;
    if (lane == 31)
        base = atomicAdd(isE ? &g_curE : &g_curV, inc);
    base = __shfl_sync(0xffffffffu, base, 31);
    int off = base + inc - c;
    if (isE) {
        g_offE[i] = off;
        g_lenE[i] = c;
        g_escale[i] = degE[i] / fmaxf((float)c, 1.0f);
        g_cntE[i] = 0;
    } else {
        g_offV[i - NE_] = off;
        g_lenV[i - NE_] = c;
        g_cntV[i - NE_] = 0;
    }
}

__global__ void build_adj_k(const int4* __restrict__ vertex4, const int4* __restrict__ edges4) {
    int i = blockIdx.x * blockDim.x + threadIdx.x;
    if (i < NNZ_ / 4) {
        int4 v = vertex4[i];
        int4 e = edges4[i];
        int oe0 = g_offE[e.x], oe1 = g_offE[e.y], oe2 = g_offE[e.z], oe3 = g_offE[e.w];
        int ov0 = g_offV[v.x], ov1 = g_offV[v.y], ov2 = g_offV[v.z], ov3 = g_offV[v.w];
        int pe0 = oe0 + atomicAdd(&g_cntE[e.x], 1);
        int pe1 = oe1 + atomicAdd(&g_cntE[e.y], 1);
        int pe2 = oe2 + atomicAdd(&g_cntE[e.z], 1);
        int pe3 = oe3 + atomicAdd(&g_cntE[e.w], 1);
        int pv0 = ov0 + atomicAdd(&g_cntV[v.x], 1);
        int pv1 = ov1 + atomicAdd(&g_cntV[v.y], 1);
        int pv2 = ov2 + atomicAdd(&g_cntV[v.z], 1);
        int pv3 = ov3 + atomicAdd(&g_cntV[v.w], 1);
        g_adjE[pe0] = v.x; g_adjE[pe1] = v.y; g_adjE[pe2] = v.z; g_adjE[pe3] = v.w;
        g_adjV[pv0] = e.x; g_adjV[pv1] = e.y; g_adjV[pv2] = e.z; g_adjV[pv3] = e.w;
    }
}

// ---------------- vertex -> edge mean (warp per edge, float2 lanes) ----------------
__global__ void __launch_bounds__(256) agg_ve_k() {
    int e = blockIdx.x * 8 + (threadIdx.x >> 5);
    if (e >= NE_) return;
    int lane = threadIdx.x & 31;
    int beg = g_offE[e], len = g_lenE[e];
    float ax = 0.f, ay = 0.f;
    const float* __restrict__ X = g_X;
    int j = 0;
    for (; j + 8 <= len; j += 8) {
        int i0 = g_adjE[beg + j + 0], i1 = g_adjE[beg + j + 1];
        int i2 = g_adjE[beg + j + 2], i3 = g_adjE[beg + j + 3];
        int i4 = g_adjE[beg + j + 4], i5 = g_adjE[beg + j + 5];
        int i6 = g_adjE[beg + j + 6], i7 = g_adjE[beg + j + 7];
        float2 t0 = __ldg((const float2*)&X[i0 * NHID_ + lane * 2]);
        float2 t1 = __ldg((const float2*)&X[i1 * NHID_ + lane * 2]);
        float2 t2 = __ldg((const float2*)&X[i2 * NHID_ + lane * 2]);
        float2 t3 = __ldg((const float2*)&X[i3 * NHID_ + lane * 2]);
        float2 t4 = __ldg((const float2*)&X[i4 * NHID_ + lane * 2]);
        float2 t5 = __ldg((const float2*)&X[i5 * NHID_ + lane * 2]);
        float2 t6 = __ldg((const float2*)&X[i6 * NHID_ + lane * 2]);
        float2 t7 = __ldg((const float2*)&X[i7 * NHID_ + lane * 2]);
        ax += ((t0.x + t1.x) + (t2.x + t3.x)) + ((t4.x + t5.x) + (t6.x + t7.x));
        ay += ((t0.y + t1.y) + (t2.y + t3.y)) + ((t4.y + t5.y) + (t6.y + t7.y));
    }
    for (; j < len; j++) {
        int v = g_adjE[beg + j];
        float2 t = __ldg((const float2*)&X[v * NHID_ + lane * 2]);
        ax += t.x; ay += t.y;
    }
    float s = g_escale[e];
    float2 r; r.x = ax * s; r.y = ay * s;
    *(float2*)&g_Xe[e * NHID_ + lane * 2] = r;
}

// ---------------- FUSED: edge->vertex sum, *degV, L2 norm, alpha-mix,
//                  Xi@W (W in SMEM), beta-mix, relu -> g_X  ----------------
// Warp per vertex; xi staged in 256B smem per warp; __syncwarp only.
__global__ void __launch_bounds__(256) agg_ev_gemm_k(
    const float* __restrict__ degV, const float* __restrict__ W,
    float c0, float c1)
{
    __shared__ __align__(16) float Wsm[64 * 64];     // W[k][c], 16KB
    __shared__ __align__(16) float srow[8][64];      // xi row per warp

    int tid = threadIdx.x;
    // cooperative W load (256 threads x 16 floats)
    #pragma unroll
    for (int i = 0; i < 4; i++)
        *(float4*)&Wsm[tid * 4 + i * 1024] = *(const float4*)&W[tid * 4 + i * 1024];
    __syncthreads();

    int wid = tid >> 5;
    int v = blockIdx.x * 8 + wid;
    if (v >= N_V) return;
    int lane = tid & 31;
    int beg = g_offV[v], len = g_lenV[v];
    float ax = 0.f, ay = 0.f;
    const float* __restrict__ Xe = g_Xe;
    int j = 0;
    for (; j + 8 <= len; j += 8) {
        int e0 = g_adjV[beg + j + 0], e1 = g_adjV[beg + j + 1];
        int e2 = g_adjV[beg + j + 2], e3 = g_adjV[beg + j + 3];
        int e4 = g_adjV[beg + j + 4], e5 = g_adjV[beg + j + 5];
        int e6 = g_adjV[beg + j + 6], e7 = g_adjV[beg + j + 7];
        float2 t0 = __ldg((const float2*)&Xe[e0 * NHID_ + lane * 2]);
        float2 t1 = __ldg((const float2*)&Xe[e1 * NHID_ + lane * 2]);
        float2 t2 = __ldg((const float2*)&Xe[e2 * NHID_ + lane * 2]);
        float2 t3 = __ldg((const float2*)&Xe[e3 * NHID_ + lane * 2]);
        float2 t4 = __ldg((const float2*)&Xe[e4 * NHID_ + lane * 2]);
        float2 t5 = __ldg((const float2*)&Xe[e5 * NHID_ + lane * 2]);
        float2 t6 = __ldg((const float2*)&Xe[e6 * NHID_ + lane * 2]);
        float2 t7 = __ldg((const float2*)&Xe[e7 * NHID_ + lane * 2]);
        ax += ((t0.x + t1.x) + (t2.x + t3.x)) + ((t4.x + t5.x) + (t6.x + t7.x));
        ay += ((t0.y + t1.y) + (t2.y + t3.y)) + ((t4.y + t5.y) + (t6.y + t7.y));
    }
    for (; j < len; j++) {
        int e = g_adjV[beg + j];
        float2 t = __ldg((const float2*)&Xe[e * NHID_ + lane * 2]);
        ax += t.x; ay += t.y;
    }
    float dv = __ldg(&degV[v]);
    ax *= dv; ay *= dv;
    float ss = ax * ax + ay * ay;
    #pragma unroll
    for (int o = 16; o; o >>= 1) ss += __shfl_xor_sync(0xffffffffu, ss, o);
    float scale = (ss > 0.f) ? rsqrtf(ss) : 0.f;
    float2 x0 = *(const float2*)&g_X0[(size_t)v * NHID_ + lane * 2];
    float xix = 0.9f * ax * scale + 0.1f * x0.x;
    float xiy = 0.9f * ay * scale + 0.1f * x0.y;

    // stage xi row for this warp, then warp-local GEMV: out[c] = dot(xi, W[:,c])
    *(float2*)&srow[wid][lane * 2] = make_float2(xix, xiy);
    __syncwarp();

    float d0 = 0.f, d1 = 0.f;              // this lane's two output columns
    const int c = lane * 2;
    #pragma unroll 4
    for (int k4 = 0; k4 < 16; k4++) {
        float4 xk = *(const float4*)&srow[wid][k4 * 4];
        float2 w0 = *(const float2*)&Wsm[(k4 * 4 + 0) * 64 + c];
        float2 w1 = *(const float2*)&Wsm[(k4 * 4 + 1) * 64 + c];
        float2 w2 = *(const float2*)&Wsm[(k4 * 4 + 2) * 64 + c];
        float2 w3 = *(const float2*)&Wsm[(k4 * 4 + 3) * 64 + c];
        d0 += xk.x * w0.x + xk.y * w1.x + xk.z * w2.x + xk.w * w3.x;
        d1 += xk.x * w0.y + xk.y * w1.y + xk.z * w2.y + xk.w * w3.y;
    }
    float2 r;
    r.x = fmaxf(c0 * xix + c1 * d0, 0.f);
    r.y = fmaxf(c0 * xiy + c1 * d1, 0.f);
    *(float2*)&g_X[(size_t)v * NHID_ + lane * 2] = r;
}

// ---------------- tiled GEMM: 64-row tile, 128 threads, 4x8 micro-tile ----------------
// MODE 0: X = relu(A@W + b), also copy to X0.   (A = external x, K=128, NCOL=64)
// MODE 2: out = log_softmax(g_X@W + b).          (K=64, NCOL=40)
template <int K, int NCOL, int MODE>
__global__ void __launch_bounds__(128) gemm_k(
    const float* __restrict__ Aext, const float* __restrict__ W,
    const float* __restrict__ bias, float* __restrict__ outext)
{
    constexpr int KC = 64;
    constexpr int KP = KC + 4;
    constexpr int NP = (NCOL + 7) & ~3;
    __shared__ float As[64 * KP];
    __shared__ float Wsm[KC * NP];
    __shared__ float Ls[(MODE == 2) ? 64 * NCOL : 1];

    const float* A = (MODE == 0) ? Aext : g_X;
    const int M = N_V;
    int tid = threadIdx.x;
    int row0 = blockIdx.x * 64;
    int tx = tid & 7;
    int ty = tid >> 3;
    bool active = (NCOL == 64) || (tx * 8 < NCOL);

    float acc[4][8] = {};

    for (int kc = 0; kc < K; kc += KC) {
        for (int idx = tid; idx < KC * (NCOL / 4); idx += 128) {
            int k = idx / (NCOL / 4), c4 = idx - k * (NCOL / 4);
            *(float4*)&Wsm[k * NP + c4 * 4] = *(const float4*)&W[(kc + k) * NCOL + c4 * 4];
        }
        for (int idx = tid; idx < 64 * (KC / 4); idx += 128) {
            int r = idx / (KC / 4), k4 = idx - r * (KC / 4);
            int row = row0 + r;
            float4 v = make_float4(0.f, 0.f, 0.f, 0.f);
            if (row < M) v = *(const float4*)&A[(size_t)row * K + kc + k4 * 4];
            *(float4*)&As[r * KP + k4 * 4] = v;
        }
        __syncthreads();
        if (active) {
            #pragma unroll 4
            for (int k = 0; k < KC; k++) {
                float4 w0 = *(const float4*)&Wsm[k * NP + tx * 8];
                float4 w1 = *(const float4*)&Wsm[k * NP + tx * 8 + 4];
                #pragma unroll
                for (int i = 0; i < 4; i++) {
                    float a = As[(ty * 4 + i) * KP + k];
                    acc[i][0] += a * w0.x; acc[i][1] += a * w0.y;
                    acc[i][2] += a * w0.z; acc[i][3] += a * w0.w;
                    acc[i][4] += a * w1.x; acc[i][5] += a * w1.y;
                    acc[i][6] += a * w1.z; acc[i][7] += a * w1.w;
                }
            }
        }
        __syncthreads();
    }

    if (MODE == 0) {
        float4 ba = *(const float4*)&bias[tx * 8];
        float4 bb = *(const float4*)&bias[tx * 8 + 4];
        #pragma unroll
        for (int i = 0; i < 4; i++) {
            int row = row0 + ty * 4 + i;
            if (row < M) {
                float4 ra, rb;
                ra.x = fmaxf(acc[i][0] + ba.x, 0.f);
                ra.y = fmaxf(acc[i][1] + ba.y, 0.f);
                ra.z = fmaxf(acc[i][2] + ba.z, 0.f);
                ra.w = fmaxf(acc[i][3] + ba.w, 0.f);
                rb.x = fmaxf(acc[i][4] + bb.x, 0.f);
                rb.y = fmaxf(acc[i][5] + bb.y, 0.f);
                rb.z = fmaxf(acc[i][6] + bb.z, 0.f);
                rb.w = fmaxf(acc[i][7] + bb.w, 0.f);
                *(float4*)&g_X [(size_t)row * NHID_ + tx * 8]     = ra;
                *(float4*)&g_X [(size_t)row * NHID_ + tx * 8 + 4] = rb;
                *(float4*)&g_X0[(size_t)row * NHID_ + tx * 8]     = ra;
                *(float4*)&g_X0[(size_t)row * NHID_ + tx * 8 + 4] = rb;
            }
        }
    } else {  // MODE 2: logits + fused log_softmax
        if (active) {
            #pragma unroll
            for (int i = 0; i < 4; i++) {
                int r = ty * 4 + i;
                #pragma unroll
                for (int j = 0; j < 8; j++)
                    Ls[r * NCOL + tx * 8 + j] = acc[i][j] + __ldg(bias + tx * 8 + j);
            }
        }
        __syncthreads();
        if (tid < 64) {
            int row = row0 + tid;
            if (row < M) {
                float mx = -1e30f;
                #pragma unroll
                for (int c = 0; c < NCOL; c++) mx = fmaxf(mx, Ls[tid * NCOL + c]);
                float s = 0.f;
                #pragma unroll
                for (int c = 0; c < NCOL; c++) s += __expf(Ls[tid * NCOL + c] - mx);
                float lse = mx + __logf(s);
                #pragma unroll
                for (int c = 0; c < NCOL; c++)
                    outext[(size_t)row * NCOL + c] = Ls[tid * NCOL + c] - lse;
            }
        }
    }
}

// ---------------- launch ----------------
extern "C" void kernel_launch(void* const* d_in, const int* in_sizes, int n_in,
                              void* d_out, int out_size)
{
    const float* x    = (const float*)d_in[0];
    const float* degE = (const float*)d_in[1];
    const float* degV = (const float*)d_in[2];
    const float* W0   = (const float*)d_in[3];
    const float* b0   = (const float*)d_in[4];
    const float* Ws   = (const float*)d_in[5];
    const float* Wout = (const float*)d_in[6];
    const float* bout = (const float*)d_in[7];
    const int* vertex = (const int*)d_in[8];
    const int* edges  = (const int*)d_in[9];
    float* out = (float*)d_out;

    (void)in_sizes; (void)n_in; (void)out_size;

    const int GB = (N_V + 63) / 64;
    const int Q4 = NNZ_ / 4;

    // CSR/CSC build
    zero_cnt_k<<<(N_V + 255) / 256, 256>>>();
    hist_k<<<(Q4 + 255) / 256, 256>>>((const int4*)vertex, (const int4*)edges);
    alloc_k<<<(NE_ + N_V + 255) / 256, 256>>>(degE);
    build_adj_k<<<(Q4 + 255) / 256, 256>>>((const int4*)vertex, (const int4*)edges);

    // X = relu(x @ W0 + b0); X0 = X
    gemm_k<128, 64, 0><<<GB, 128>>>(x, W0, b0, nullptr);

    for (int i = 0; i < NLAYER_; i++) {
        float beta = logf(0.5f / (float)(i + 1) + 1.0f);
        agg_ve_k<<<(NE_ + 7) / 8, 256>>>();
        agg_ev_gemm_k<<<(N_V + 7) / 8, 256>>>(degV, Ws + (size_t)i * NHID_ * NHID_,
                                              1.0f - beta, beta);
    }

    // log_softmax(X @ Wout + bout)
    gemm_k<64, 40, 2><<<GB, 128>>>(nullptr, Wout, bout, out);
}

// round 10
// speedup vs baseline: 1.3890x; 1.1309x over previous
#include <cuda_runtime.h>
#include <math.h>

#define N_V    100000
#define NE_    20000
#define NNZ_   1600000
#define NFEAT_ 128
#define NHID_  64
#define NCLASS_ 40
#define NLAYER_ 4

// packed fp32x2 helpers (FFMA2 is only reachable via PTX; bitwise IEEE fp32 rn)
#define PACK_AA(ap, a) \
    asm("mov.b64 %0, {%1, %1};" : "=l"(ap) : "f"(a))
#define FMA2(acc, a, b) \
    asm("fma.rn.f32x2 %0, %1, %2, %0;" : "+l"(acc) : "l"(a), "l"(b))
#define UNPACK2(lo, hi, p) \
    asm("mov.b64 {%0, %1}, %2;" : "=f"(lo), "=f"(hi) : "l"(p))

// ---------------- device scratch (static, no allocation) ----------------
__device__ float g_X [N_V * NHID_];   // current features
__device__ float g_X0[N_V * NHID_];   // residual anchor
__device__ float g_Xe[NE_ * NHID_];   // edge features (pre-scaled by degE/count)
__device__ float g_escale[NE_];
__device__ int   g_cntE[NE_];
__device__ int   g_cntV[N_V];
__device__ int   g_lenE[NE_];
__device__ int   g_lenV[N_V];
__device__ int   g_offE[NE_];
__device__ int   g_offV[N_V];
__device__ int   g_curE;
__device__ int   g_curV;
__device__ int   g_adjE[NNZ_];        // members (vertex ids) per edge
__device__ int   g_adjV[NNZ_];        // incident edges per vertex

// ---------------- CSR build ----------------
__global__ void zero_cnt_k() {
    int i = blockIdx.x * blockDim.x + threadIdx.x;
    if (i < NE_) g_cntE[i] = 0;
    if (i < N_V) g_cntV[i] = 0;
    if (i == 0) { g_curE = 0; g_curV = 0; }
}

__global__ void hist_k(const int4* __restrict__ vertex4, const int4* __restrict__ edges4) {
    int i = blockIdx.x * blockDim.x + threadIdx.x;
    if (i < NNZ_ / 4) {
        int4 e = edges4[i];
        int4 v = vertex4[i];
        atomicAdd(&g_cntE[e.x], 1);
        atomicAdd(&g_cntE[e.y], 1);
        atomicAdd(&g_cntE[e.z], 1);
        atomicAdd(&g_cntE[e.w], 1);
        atomicAdd(&g_cntV[v.x], 1);
        atomicAdd(&g_cntV[v.y], 1);
        atomicAdd(&g_cntV[v.z], 1);
        atomicAdd(&g_cntV[v.w], 1);
    }
}

// warp-aggregated bump allocation of CSR offsets (segment order arbitrary but
// valid; per-segment sums are order-independent).
__global__ void alloc_k(const float* __restrict__ degE) {
    int i = blockIdx.x * blockDim.x + threadIdx.x;
    const int n = NE_ + N_V;
    if (i >= n) return;           // NE_ and n are multiples of 32
    int lane = threadIdx.x & 31;
    bool isE = (i < NE_);
    int c = isE ? g_cntE[i] : g_cntV[i - NE_];
    int inc = c;
    #pragma unroll
    for (int o = 1; o < 32; o <<= 1) {
        int t = __shfl_up_sync(0xffffffffu, inc, o);
        if (lane >= o) inc += t;
    }
    int base = 0;
    if (lane == 31)
        base = atomicAdd(isE ? &g_curE : &g_curV, inc);
    base = __shfl_sync(0xffffffffu, base, 31);
    int off = base + inc - c;
    if (isE) {
        g_offE[i] = off;
        g_lenE[i] = c;
        g_escale[i] = degE[i] / fmaxf((float)c, 1.0f);
        g_cntE[i] = 0;
    } else {
        g_offV[i - NE_] = off;
        g_lenV[i - NE_] = c;
        g_cntV[i - NE_] = 0;
    }
}

__global__ void build_adj_k(const int4* __restrict__ vertex4, const int4* __restrict__ edges4) {
    int i = blockIdx.x * blockDim.x + threadIdx.x;
    if (i < NNZ_ / 4) {
        int4 v = vertex4[i];
        int4 e = edges4[i];
        int oe0 = g_offE[e.x], oe1 = g_offE[e.y], oe2 = g_offE[e.z], oe3 = g_offE[e.w];
        int ov0 = g_offV[v.x], ov1 = g_offV[v.y], ov2 = g_offV[v.z], ov3 = g_offV[v.w];
        int pe0 = oe0 + atomicAdd(&g_cntE[e.x], 1);
        int pe1 = oe1 + atomicAdd(&g_cntE[e.y], 1);
        int pe2 = oe2 + atomicAdd(&g_cntE[e.z], 1);
        int pe3 = oe3 + atomicAdd(&g_cntE[e.w], 1);
        int pv0 = ov0 + atomicAdd(&g_cntV[v.x], 1);
        int pv1 = ov1 + atomicAdd(&g_cntV[v.y], 1);
        int pv2 = ov2 + atomicAdd(&g_cntV[v.z], 1);
        int pv3 = ov3 + atomicAdd(&g_cntV[v.w], 1);
        g_adjE[pe0] = v.x; g_adjE[pe1] = v.y; g_adjE[pe2] = v.z; g_adjE[pe3] = v.w;
        g_adjV[pv0] = e.x; g_adjV[pv1] = e.y; g_adjV[pv2] = e.z; g_adjV[pv3] = e.w;
    }
}

// ---------------- vertex -> edge mean (warp per edge, float2 lanes) ----------------
__global__ void __launch_bounds__(256) agg_ve_k() {
    int e = blockIdx.x * 8 + (threadIdx.x >> 5);
    if (e >= NE_) return;
    int lane = threadIdx.x & 31;
    int beg = g_offE[e], len = g_lenE[e];
    float ax = 0.f, ay = 0.f;
    const float* __restrict__ X = g_X;
    int j = 0;
    for (; j + 8 <= len; j += 8) {
        int i0 = g_adjE[beg + j + 0], i1 = g_adjE[beg + j + 1];
        int i2 = g_adjE[beg + j + 2], i3 = g_adjE[beg + j + 3];
        int i4 = g_adjE[beg + j + 4], i5 = g_adjE[beg + j + 5];
        int i6 = g_adjE[beg + j + 6], i7 = g_adjE[beg + j + 7];
        float2 t0 = __ldg((const float2*)&X[i0 * NHID_ + lane * 2]);
        float2 t1 = __ldg((const float2*)&X[i1 * NHID_ + lane * 2]);
        float2 t2 = __ldg((const float2*)&X[i2 * NHID_ + lane * 2]);
        float2 t3 = __ldg((const float2*)&X[i3 * NHID_ + lane * 2]);
        float2 t4 = __ldg((const float2*)&X[i4 * NHID_ + lane * 2]);
        float2 t5 = __ldg((const float2*)&X[i5 * NHID_ + lane * 2]);
        float2 t6 = __ldg((const float2*)&X[i6 * NHID_ + lane * 2]);
        float2 t7 = __ldg((const float2*)&X[i7 * NHID_ + lane * 2]);
        ax += ((t0.x + t1.x) + (t2.x + t3.x)) + ((t4.x + t5.x) + (t6.x + t7.x));
        ay += ((t0.y + t1.y) + (t2.y + t3.y)) + ((t4.y + t5.y) + (t6.y + t7.y));
    }
    for (; j < len; j++) {
        int v = g_adjE[beg + j];
        float2 t = __ldg((const float2*)&X[v * NHID_ + lane * 2]);
        ax += t.x; ay += t.y;
    }
    float s = g_escale[e];
    float2 r; r.x = ax * s; r.y = ay * s;
    *(float2*)&g_Xe[e * NHID_ + lane * 2] = r;
}

// ---------------- edge -> vertex sum (warp per vertex, float2 lanes),
//                  fused *degV, L2 norm (shuffle-only), alpha-mix ----------------
__global__ void __launch_bounds__(256) agg_ev_k(const float* __restrict__ degV) {
    int v = blockIdx.x * 8 + (threadIdx.x >> 5);
    if (v >= N_V) return;
    int lane = threadIdx.x & 31;
    int beg = g_offV[v], len = g_lenV[v];
    float ax = 0.f, ay = 0.f;
    const float* __restrict__ Xe = g_Xe;
    int j = 0;
    for (; j + 8 <= len; j += 8) {
        int e0 = g_adjV[beg + j + 0], e1 = g_adjV[beg + j + 1];
        int e2 = g_adjV[beg + j + 2], e3 = g_adjV[beg + j + 3];
        int e4 = g_adjV[beg + j + 4], e5 = g_adjV[beg + j + 5];
        int e6 = g_adjV[beg + j + 6], e7 = g_adjV[beg + j + 7];
        float2 t0 = __ldg((const float2*)&Xe[e0 * NHID_ + lane * 2]);
        float2 t1 = __ldg((const float2*)&Xe[e1 * NHID_ + lane * 2]);
        float2 t2 = __ldg((const float2*)&Xe[e2 * NHID_ + lane * 2]);
        float2 t3 = __ldg((const float2*)&Xe[e3 * NHID_ + lane * 2]);
        float2 t4 = __ldg((const float2*)&Xe[e4 * NHID_ + lane * 2]);
        float2 t5 = __ldg((const float2*)&Xe[e5 * NHID_ + lane * 2]);
        float2 t6 = __ldg((const float2*)&Xe[e6 * NHID_ + lane * 2]);
        float2 t7 = __ldg((const float2*)&Xe[e7 * NHID_ + lane * 2]);
        ax += ((t0.x + t1.x) + (t2.x + t3.x)) + ((t4.x + t5.x) + (t6.x + t7.x));
        ay += ((t0.y + t1.y) + (t2.y + t3.y)) + ((t4.y + t5.y) + (t6.y + t7.y));
    }
    for (; j < len; j++) {
        int e = g_adjV[beg + j];
        float2 t = __ldg((const float2*)&Xe[e * NHID_ + lane * 2]);
        ax += t.x; ay += t.y;
    }
    float dv = __ldg(&degV[v]);
    ax *= dv; ay *= dv;
    float ss = ax * ax + ay * ay;
    #pragma unroll
    for (int o = 16; o; o >>= 1) ss += __shfl_xor_sync(0xffffffffu, ss, o);
    float scale = (ss > 0.f) ? rsqrtf(ss) : 0.f;
    float2 x0 = *(const float2*)&g_X0[(size_t)v * NHID_ + lane * 2];
    float2 r;
    r.x = 0.9f * ax * scale + 0.1f * x0.x;
    r.y = 0.9f * ay * scale + 0.1f * x0.y;
    *(float2*)&g_X[(size_t)v * NHID_ + lane * 2] = r;
}

// ---------------- tiled GEMM: 64-row tile, 128 threads, 4x8 micro-tile,
//                  packed fma.rn.f32x2 inner loop ----------------
// MODE 0: X = relu(A@W + b), also copy to X0.   (A = external x, K=128, NCOL=64)
// MODE 1: X = relu(c0*Xi + c1*(Xi@W)), in-place. (K=NCOL=64)
// MODE 2: out = log_softmax(g_X@W + b).          (K=64, NCOL=40)
template <int K, int NCOL, int MODE>
__global__ void __launch_bounds__(128) gemm_k(
    const float* __restrict__ Aext, const float* __restrict__ W,
    const float* __restrict__ bias, float* __restrict__ outext,
    float c0, float c1)
{
    constexpr int KC = 64;
    constexpr int KP = KC + 4;
    constexpr int NP = (NCOL + 7) & ~3;   // 68 / 44; NP*4 bytes is a 16-multiple
    __shared__ __align__(16) float As[64 * KP];
    __shared__ __align__(16) float Wsm[KC * NP];
    __shared__ float Ls[(MODE == 2) ? 64 * NCOL : 1];

    const float* A = (MODE == 0) ? Aext : g_X;
    const int M = N_V;
    int tid = threadIdx.x;
    int row0 = blockIdx.x * 64;
    int tx = tid & 7;
    int ty = tid >> 3;
    bool active = (NCOL == 64) || (tx * 8 < NCOL);

    unsigned long long accp[4][4] = {};   // 4 rows x 4 packed col-pairs

    for (int kc = 0; kc < K; kc += KC) {
        for (int idx = tid; idx < KC * (NCOL / 4); idx += 128) {
            int k = idx / (NCOL / 4), c4 = idx - k * (NCOL / 4);
            *(float4*)&Wsm[k * NP + c4 * 4] = *(const float4*)&W[(kc + k) * NCOL + c4 * 4];
        }
        for (int idx = tid; idx < 64 * (KC / 4); idx += 128) {
            int r = idx / (KC / 4), k4 = idx - r * (KC / 4);
            int row = row0 + r;
            float4 v = make_float4(0.f, 0.f, 0.f, 0.f);
            if (row < M) v = *(const float4*)&A[(size_t)row * K + kc + k4 * 4];
            *(float4*)&As[r * KP + k4 * 4] = v;
        }
        __syncthreads();
        if (active) {
            #pragma unroll 4
            for (int k = 0; k < KC; k++) {
                // W row slice as packed f32x2 pairs (bitwise-identical layout)
                const ulonglong2* wp = (const ulonglong2*)&Wsm[k * NP + tx * 8];
                ulonglong2 wa = wp[0];   // cols 0-3 (two pairs)
                ulonglong2 wb = wp[1];   // cols 4-7
                #pragma unroll
                for (int i = 0; i < 4; i++) {
                    float a = As[(ty * 4 + i) * KP + k];
                    unsigned long long ap;
                    PACK_AA(ap, a);
                    FMA2(accp[i][0], ap, wa.x);
                    FMA2(accp[i][1], ap, wa.y);
                    FMA2(accp[i][2], ap, wb.x);
                    FMA2(accp[i][3], ap, wb.y);
                }
            }
        }
        __syncthreads();
    }

    // unpack accumulators
    float acc[4][8];
    #pragma unroll
    for (int i = 0; i < 4; i++)
        #pragma unroll
        for (int j = 0; j < 4; j++)
            UNPACK2(acc[i][2 * j], acc[i][2 * j + 1], accp[i][j]);

    if (MODE == 0) {
        float4 ba = *(const float4*)&bias[tx * 8];
        float4 bb = *(const float4*)&bias[tx * 8 + 4];
        #pragma unroll
        for (int i = 0; i < 4; i++) {
            int row = row0 + ty * 4 + i;
            if (row < M) {
                float4 ra, rb;
                ra.x = fmaxf(acc[i][0] + ba.x, 0.f);
                ra.y = fmaxf(acc[i][1] + ba.y, 0.f);
                ra.z = fmaxf(acc[i][2] + ba.z, 0.f);
                ra.w = fmaxf(acc[i][3] + ba.w, 0.f);
                rb.x = fmaxf(acc[i][4] + bb.x, 0.f);
                rb.y = fmaxf(acc[i][5] + bb.y, 0.f);
                rb.z = fmaxf(acc[i][6] + bb.z, 0.f);
                rb.w = fmaxf(acc[i][7] + bb.w, 0.f);
                *(float4*)&g_X [(size_t)row * NHID_ + tx * 8]     = ra;
                *(float4*)&g_X [(size_t)row * NHID_ + tx * 8 + 4] = rb;
                *(float4*)&g_X0[(size_t)row * NHID_ + tx * 8]     = ra;
                *(float4*)&g_X0[(size_t)row * NHID_ + tx * 8 + 4] = rb;
            }
        }
    } else if (MODE == 1) {
        #pragma unroll
        for (int i = 0; i < 4; i++) {
            int r = ty * 4 + i;
            int row = row0 + r;
            if (row < M) {
                float4 ra, rb;
                ra.x = fmaxf(c0 * As[r * KP + tx * 8 + 0] + c1 * acc[i][0], 0.f);
                ra.y = fmaxf(c0 * As[r * KP + tx * 8 + 1] + c1 * acc[i][1], 0.f);
                ra.z = fmaxf(c0 * As[r * KP + tx * 8 + 2] + c1 * acc[i][2], 0.f);
                ra.w = fmaxf(c0 * As[r * KP + tx * 8 + 3] + c1 * acc[i][3], 0.f);
                rb.x = fmaxf(c0 * As[r * KP + tx * 8 + 4] + c1 * acc[i][4], 0.f);
                rb.y = fmaxf(c0 * As[r * KP + tx * 8 + 5] + c1 * acc[i][5], 0.f);
                rb.z = fmaxf(c0 * As[r * KP + tx * 8 + 6] + c1 * acc[i][6], 0.f);
                rb.w = fmaxf(c0 * As[r * KP + tx * 8 + 7] + c1 * acc[i][7], 0.f);
                *(float4*)&g_X[(size_t)row * NHID_ + tx * 8]     = ra;
                *(float4*)&g_X[(size_t)row * NHID_ + tx * 8 + 4] = rb;
            }
        }
    } else {  // MODE 2: logits + fused log_softmax
        if (active) {
            #pragma unroll
            for (int i = 0; i < 4; i++) {
                int r = ty * 4 + i;
                #pragma unroll
                for (int j = 0; j < 8; j++)
                    Ls[r * NCOL + tx * 8 + j] = acc[i][j] + __ldg(bias + tx * 8 + j);
            }
        }
        __syncthreads();
        if (tid < 64) {
            int row = row0 + tid;
            if (row < M) {
                float mx = -1e30f;
                #pragma unroll
                for (int c = 0; c < NCOL; c++) mx = fmaxf(mx, Ls[tid * NCOL + c]);
                float s = 0.f;
                #pragma unroll
                for (int c = 0; c < NCOL; c++) s += __expf(Ls[tid * NCOL + c] - mx);
                float lse = mx + __logf(s);
                #pragma unroll
                for (int c = 0; c < NCOL; c++)
                    outext[(size_t)row * NCOL + c] = Ls[tid * NCOL + c] - lse;
            }
        }
    }
}

// ---------------- launch ----------------
extern "C" void kernel_launch(void* const* d_in, const int* in_sizes, int n_in,
                              void* d_out, int out_size)
{
    const float* x    = (const float*)d_in[0];
    const float* degE = (const float*)d_in[1];
    const float* degV = (const float*)d_in[2];
    const float* W0   = (const float*)d_in[3];
    const float* b0   = (const float*)d_in[4];
    const float* Ws   = (const float*)d_in[5];
    const float* Wout = (const float*)d_in[6];
    const float* bout = (const float*)d_in[7];
    const int* vertex = (const int*)d_in[8];
    const int* edges  = (const int*)d_in[9];
    float* out = (float*)d_out;

    (void)in_sizes; (void)n_in; (void)out_size;

    const int GB = (N_V + 63) / 64;
    const int Q4 = NNZ_ / 4;

    // CSR/CSC build
    zero_cnt_k<<<(N_V + 255) / 256, 256>>>();
    hist_k<<<(Q4 + 255) / 256, 256>>>((const int4*)vertex, (const int4*)edges);
    alloc_k<<<(NE_ + N_V + 255) / 256, 256>>>(degE);
    build_adj_k<<<(Q4 + 255) / 256, 256>>>((const int4*)vertex, (const int4*)edges);

    // X = relu(x @ W0 + b0); X0 = X
    gemm_k<128, 64, 0><<<GB, 128>>>(x, W0, b0, nullptr, 0.f, 0.f);

    for (int i = 0; i < NLAYER_; i++) {
        float beta = logf(0.5f / (float)(i + 1) + 1.0f);
        agg_ve_k<<<(NE_ + 7) / 8, 256>>>();
        agg_ev_k<<<(N_V + 7) / 8, 256>>>(degV);
        gemm_k<64, 64, 1><<<GB, 128>>>(nullptr, Ws + (size_t)i * NHID_ * NHID_,
                                       nullptr, nullptr, 1.0f - beta, beta);
    }

    // log_softmax(X @ Wout + bout)
    gemm_k<64, 40, 2><<<GB, 128>>>(nullptr, Wout, bout, out, 0.f, 0.f);
}